// round 3
// baseline (speedup 1.0000x reference)
#include <cuda_runtime.h>
#include <cmath>
#include <complex>
#include <algorithm>

// ----------------------------------------------------------------------------
// Problem constants
// ----------------------------------------------------------------------------
#define NNODES   50000
#define C_DIM    128
#define M_DIM    9
#define B_NODES  8
#define THREADS  512

#define SX_F     (B_NODES * M_DIM * C_DIM)   // 9216 floats (x tile; later t tile)
#define SWA_ROW4 129                         // float4 per kpair row (128 + 1 pad)
#define SWA_F    (64 * SWA_ROW4 * 4)         // 33024 floats
#define SWC_ROW2 129                         // float2 per kpair row (128 + 1 pad)
#define SMEM_BYTES ((SX_F + SWA_F) * 4)      // 168960 B

typedef unsigned long long ull;

// Wigner-3j tables (alpha folded in), kernel arg.
struct W3J {
    float w220[25];
    float w121[45];
    float w112[45];
};

// ----------------------------------------------------------------------------
// Host-side Wigner 3j (literal translation of the reference, double precision)
// ----------------------------------------------------------------------------
namespace hw3j {
typedef std::complex<double> cd;

static inline double fact(int n) { double r = 1.0; for (int i = 2; i <= n; ++i) r *= (double)i; return r; }

static double su2_cg(int j1, int m1, int j2, int m2, int j3, int m3) {
    if (m1 + m2 != m3) return 0.0;
    int vmin = std::max(std::max(-j1 + j2 + m3, -j1 + m1), 0);
    int vmax = std::min(std::min(j2 + j3 + m1, j3 - j1 + j2), j3 + m3);
    double pref = std::sqrt((2.0 * j3 + 1.0)
        * fact(j3 + j1 - j2) * fact(j3 - j1 + j2) * fact(j1 + j2 - j3) / fact(j1 + j2 + j3 + 1)
        * fact(j3 + m3) * fact(j3 - m3)
        / (fact(j1 - m1) * fact(j1 + m1) * fact(j2 - m2) * fact(j2 + m2)));
    double s = 0.0;
    for (int v = vmin; v <= vmax; ++v) {
        double sgn = ((v + j2 + m2) & 1) ? -1.0 : 1.0;
        s += sgn / fact(v) * fact(j2 + j3 + m1 - v) * fact(j1 - m1 + v)
             / (fact(j3 - j1 + j2 - v) * fact(j3 + m3 - v) * fact(v + j1 - j2 - m3));
    }
    return pref * s;
}

static void qmat(int l, cd q[5][5]) {
    for (int a = 0; a < 5; ++a) for (int b = 0; b < 5; ++b) q[a][b] = cd(0, 0);
    const double is2 = 1.0 / std::sqrt(2.0);
    for (int m = -l; m < 0; ++m) {
        q[l + m][l - m] = cd(is2, 0.0);
        q[l + m][l + m] = cd(0.0, -is2);
    }
    q[l][l] = cd(1.0, 0.0);
    for (int m = 1; m <= l; ++m) {
        double sg = (m & 1) ? -1.0 : 1.0;
        q[l + m][l + m] = cd(sg * is2, 0.0);
        q[l + m][l - m] = cd(0.0, sg * is2);
    }
    cd ph;
    switch (l & 3) {
        case 0: ph = cd( 1,  0); break;
        case 1: ph = cd( 0, -1); break;
        case 2: ph = cd(-1,  0); break;
        default: ph = cd(0,  1); break;
    }
    for (int a = 0; a < 2 * l + 1; ++a) for (int b = 0; b < 2 * l + 1; ++b) q[a][b] *= ph;
}

static void wig3j(int l1, int l2, int l3, float* out) {
    const int d1 = 2 * l1 + 1, d2 = 2 * l2 + 1, d3 = 2 * l3 + 1;
    cd Q1[5][5], Q2[5][5], Q3[5][5];
    qmat(l1, Q1); qmat(l2, Q2); qmat(l3, Q3);
    static cd Csu2[5][5][5];
    for (int i = 0; i < d1; ++i)
        for (int k = 0; k < d2; ++k)
            for (int n = 0; n < d3; ++n)
                Csu2[i][k][n] = cd(su2_cg(l1, i - l1, l2, k - l2, l3, n - l3), 0.0);
    static double Cr[5][5][5];
    double nrm = 0.0;
    for (int j = 0; j < d1; ++j)
        for (int ll = 0; ll < d2; ++ll)
            for (int m = 0; m < d3; ++m) {
                cd acc(0, 0);
                for (int i = 0; i < d1; ++i)
                    for (int k = 0; k < d2; ++k)
                        for (int n = 0; n < d3; ++n)
                            acc += Q1[i][j] * Q2[k][ll] * std::conj(Q3[n][m]) * Csu2[i][k][n];
                Cr[j][ll][m] = acc.real();
                nrm += acc.real() * acc.real();
            }
    nrm = std::sqrt(nrm);
    int idx = 0;
    for (int j = 0; j < d1; ++j)
        for (int ll = 0; ll < d2; ++ll)
            for (int m = 0; m < d3; ++m)
                out[idx++] = (float)(Cr[j][ll][m] / nrm);
}

static void build(W3J& P) {
    float c220[25], c121[45], c112[45];
    wig3j(2, 2, 0, c220);
    wig3j(1, 2, 1, c121);
    wig3j(1, 1, 2, c112);
    const float a121 = std::sqrt(3.0f), a112 = std::sqrt(5.0f);
    for (int i = 0; i < 25; ++i) P.w220[i] = c220[i];
    for (int i = 0; i < 45; ++i) P.w121[i] = a121 * c121[i];
    for (int i = 0; i < 45; ++i) P.w112[i] = a112 * c112[i];
}
} // namespace hw3j

// ----------------------------------------------------------------------------
// Packed fp32 helpers
// ----------------------------------------------------------------------------
__device__ __forceinline__ void fma2(ull& acc, ull a, ull b) {
    asm("fma.rn.f32x2 %0, %1, %2, %0;" : "+l"(acc) : "l"(a), "l"(b));
}
__device__ __forceinline__ float f2lo(ull v) { return __uint_as_float((unsigned int)v); }
__device__ __forceinline__ float f2hi(ull v) { return __uint_as_float((unsigned int)(v >> 32)); }

// ----------------------------------------------------------------------------
// Fused kernel.
// Thread layout (512 threads): warp = tid>>5 (16 warps)
//   node-pair np = warp & 3         -> nodes {2np, 2np+1} of the 8-node tile
//   channel  s  = lane + 32*(warp>>2)  in 0..127
// Stage A: acc{L,R}[node 2][m 9] as f32x2 {even-k, odd-k} partial sums.
// TP: in registers (thread owns both yl[s], yr[s]).
// Stage C: t via smem (sx region reused), same GEMM scheme, 1 matrix.
// ----------------------------------------------------------------------------
__global__ __launch_bounds__(THREADS, 1)
void b2i_fused_kernel(const float* __restrict__ x,
                      const float* __restrict__ Wl, const float* __restrict__ bl,
                      const float* __restrict__ Wr, const float* __restrict__ br,
                      const float* __restrict__ Wf, const float* __restrict__ bf,
                      float* __restrict__ out, const W3J P)
{
    extern __shared__ float smem[];
    float* sx = smem;            // x tile [8][9][128]; later t tile
    float* sw = smem + SX_F;     // weight staging

    const int tid  = threadIdx.x;
    const int lane = tid & 31;
    const int warp = tid >> 5;
    const int np   = warp & 3;                   // node pair
    const int s    = lane + ((warp >> 2) << 5);  // channel 0..127
    const size_t node0 = (size_t)blockIdx.x * B_NODES;

    // ---- load x tile (coalesced float2) ----
    {
        const float2* gx = reinterpret_cast<const float2*>(x + node0 * M_DIM * C_DIM);
        float2* sx2 = reinterpret_cast<float2*>(sx);
        #pragma unroll
        for (int i = 0; i < (SX_F / 2) / THREADS; ++i)
            sx2[tid + i * THREADS] = gx[tid + i * THREADS];
    }

    const float blv = bl[s];
    const float brv = br[s];
    const float bfv = bf[s];

    // =========================================================================
    // Stage A: yl/yr linears. acc = f32x2 {even-k, odd-k} partials.
    // =========================================================================
    ull accL[2][M_DIM], accR[2][M_DIM];
    #pragma unroll
    for (int n = 0; n < 2; ++n)
        #pragma unroll
        for (int m = 0; m < M_DIM; ++m) { accL[n][m] = 0ULL; accR[n][m] = 0ULL; }

    for (int l = 0; l < 3; ++l) {
        __syncthreads();   // x-tile ready (l=0) / prev-l compute done reading sw
        // ---- stage Wl/Wr for this l: sw4[kp][ss] = {Wl[ss][2kp],Wl[ss][2kp+1],Wr[ss][2kp],Wr[ss][2kp+1]} ----
        {
            float4* sw4 = reinterpret_cast<float4*>(sw);
            #pragma unroll
            for (int i = 0; i < 16; ++i) {
                const int idx = tid + i * THREADS;     // 0..8191
                const int kp = idx & 63;
                const int ss = idx >> 6;
                const float2 a = __ldg(reinterpret_cast<const float2*>(Wl + (size_t)(l * 128 + ss) * 128 + kp * 2));
                const float2 b = __ldg(reinterpret_cast<const float2*>(Wr + (size_t)(l * 128 + ss) * 128 + kp * 2));
                sw4[kp * SWA_ROW4 + ss] = make_float4(a.x, a.y, b.x, b.y);
            }
        }
        __syncthreads();

        const int base = l * l, msz = 2 * l + 1;
        const ulonglong2* sw4u = reinterpret_cast<const ulonglong2*>(sw);
        const ulonglong2* sx4u = reinterpret_cast<const ulonglong2*>(sx);
        #pragma unroll 4
        for (int q = 0; q < 32; ++q) {             // q = group of 4 k's = 2 kpairs
            const ulonglong2 w0 = sw4u[(2 * q)     * SWA_ROW4 + s];  // {Wl pair, Wr pair} for k=4q,4q+1
            const ulonglong2 w1 = sw4u[(2 * q + 1) * SWA_ROW4 + s];  // for k=4q+2,4q+3
            #pragma unroll
            for (int n = 0; n < 2; ++n) {
                const int node = 2 * np + n;
                #pragma unroll
                for (int mm = 0; mm < msz; ++mm) {
                    const ulonglong2 xv = sx4u[(node * M_DIM + base + mm) * 32 + q];  // broadcast
                    fma2(accL[n][base + mm], xv.x, w0.x);
                    fma2(accR[n][base + mm], xv.x, w0.y);
                    fma2(accL[n][base + mm], xv.y, w1.x);
                    fma2(accR[n][base + mm], xv.y, w1.y);
                }
            }
        }
    }

    // =========================================================================
    // Stage B: merge parities, bias, CG tensor product -> t into sx region
    // =========================================================================
    __syncthreads();   // all stage-A reads of sx / sw complete
    float* st = sx;
    #pragma unroll
    for (int n = 0; n < 2; ++n) {
        const int node = 2 * np + n;
        float L[M_DIM], R[M_DIM];
        #pragma unroll
        for (int m = 0; m < M_DIM; ++m) {
            L[m] = f2lo(accL[n][m]) + f2hi(accL[n][m]);
            R[m] = f2lo(accR[n][m]) + f2hi(accR[n][m]);
        }
        L[0] += blv; R[0] += brv;

        float t[M_DIM];
        {   // (2,2,0)
            float v = 0.f;
            #pragma unroll
            for (int i = 0; i < 5; ++i)
                #pragma unroll
                for (int j = 0; j < 5; ++j)
                    v = fmaf(P.w220[i * 5 + j], L[4 + i] * R[4 + j], v);
            t[0] = v;
        }
        #pragma unroll
        for (int k = 0; k < 3; ++k) {   // (1,2,1)
            float v = 0.f;
            #pragma unroll
            for (int i = 0; i < 3; ++i)
                #pragma unroll
                for (int j = 0; j < 5; ++j)
                    v = fmaf(P.w121[(i * 5 + j) * 3 + k], L[1 + i] * R[4 + j], v);
            t[1 + k] = v;
        }
        #pragma unroll
        for (int k = 0; k < 5; ++k) {   // (1,1,2)
            float v = 0.f;
            #pragma unroll
            for (int i = 0; i < 3; ++i)
                #pragma unroll
                for (int j = 0; j < 3; ++j)
                    v = fmaf(P.w112[(i * 3 + j) * 5 + k], L[1 + i] * R[1 + j], v);
            t[4 + k] = v;
        }
        #pragma unroll
        for (int m = 0; m < M_DIM; ++m)
            st[(node * M_DIM + m) * C_DIM + s] = t[m];
    }

    // =========================================================================
    // Stage C: final linear over t (k-parity packed), same scheme, 1 matrix
    // =========================================================================
    ull acc2[2][M_DIM];
    #pragma unroll
    for (int n = 0; n < 2; ++n)
        #pragma unroll
        for (int m = 0; m < M_DIM; ++m) acc2[n][m] = 0ULL;

    for (int l = 0; l < 3; ++l) {
        __syncthreads();   // t writes done (l=0) / prev-l compute done
        // ---- stage Wf[l]: sw2[kp][ss] = {Wf[ss][2kp], Wf[ss][2kp+1]} ----
        {
            float2* sw2 = reinterpret_cast<float2*>(sw);
            #pragma unroll
            for (int i = 0; i < 16; ++i) {
                const int idx = tid + i * THREADS;
                const int kp = idx & 63;
                const int ss = idx >> 6;
                sw2[kp * SWC_ROW2 + ss] =
                    __ldg(reinterpret_cast<const float2*>(Wf + (size_t)(l * 128 + ss) * 128 + kp * 2));
            }
        }
        __syncthreads();

        const int base = l * l, msz = 2 * l + 1;
        const ull* sw2u = reinterpret_cast<const ull*>(sw);
        const ulonglong2* st4u = reinterpret_cast<const ulonglong2*>(st);
        #pragma unroll 4
        for (int q = 0; q < 32; ++q) {
            const ull w0 = sw2u[(2 * q)     * SWC_ROW2 + s];
            const ull w1 = sw2u[(2 * q + 1) * SWC_ROW2 + s];
            #pragma unroll
            for (int n = 0; n < 2; ++n) {
                const int node = 2 * np + n;
                #pragma unroll
                for (int mm = 0; mm < msz; ++mm) {
                    const ulonglong2 tv = st4u[(node * M_DIM + base + mm) * 32 + q];  // broadcast
                    fma2(acc2[n][base + mm], tv.x, w0);
                    fma2(acc2[n][base + mm], tv.y, w1);
                }
            }
        }
    }

    // ---- merge, bias, write out ----
    #pragma unroll
    for (int n = 0; n < 2; ++n) {
        const size_t node = node0 + 2 * np + n;
        #pragma unroll
        for (int m = 0; m < M_DIM; ++m) {
            float v = f2lo(acc2[n][m]) + f2hi(acc2[n][m]);
            if (m == 0) v += bfv;
            out[(node * M_DIM + m) * C_DIM + s] = v;
        }
    }
}

// ----------------------------------------------------------------------------
// Launch
// ----------------------------------------------------------------------------
extern "C" void kernel_launch(void* const* d_in, const int* in_sizes, int n_in,
                              void* d_out, int out_size)
{
    const float* x  = (const float*)d_in[0];
    const float* Wl = (const float*)d_in[1];
    const float* bl = (const float*)d_in[2];
    const float* Wr = (const float*)d_in[3];
    const float* br = (const float*)d_in[4];
    const float* Wf = (const float*)d_in[5];
    const float* bf = (const float*)d_in[6];
    float* out = (float*)d_out;

    W3J P;
    hw3j::build(P);

    cudaFuncSetAttribute(b2i_fused_kernel, cudaFuncAttributeMaxDynamicSharedMemorySize, SMEM_BYTES);

    b2i_fused_kernel<<<NNODES / B_NODES, THREADS, SMEM_BYTES>>>(
        x, Wl, bl, Wr, br, Wf, bf, out, P);
}